// round 2
// baseline (speedup 1.0000x reference)
#include <cuda_runtime.h>
#include <cuda_bf16.h>
#include <math.h>

// Shapes (fixed by the problem)
#define BATCH   2
#define SEQ     2048
#define DMODEL  1024
#define NHEAD   16
#define HDIM    64
#define BT      (BATCH * SEQ)          // 4096 rows
#define N_QKV   (3 * DMODEL)           // 3072

// Scratch (static device arrays: allowed; cudaMalloc is not)
__device__ float g_Q[BATCH * NHEAD * SEQ * HDIM];   // [b,h,t,d]
__device__ float g_K[BATCH * NHEAD * SEQ * HDIM];
__device__ float g_V[BATCH * NHEAD * SEQ * HDIM];
__device__ float g_Y[BT * DMODEL];                  // attention output, [b*t, h*64+d]
__device__ float g_cos[SEQ * HDIM];
__device__ float g_sin[SEQ * HDIM];

// ---------------------------------------------------------------------------
// RoPE cos/sin table:  emb[d] = t * base^{-fi/32},  fi = d<32 ? d : d-32
// ---------------------------------------------------------------------------
__global__ void rope_table_kernel() {
    int i = blockIdx.x * blockDim.x + threadIdx.x;   // < SEQ*HDIM
    if (i >= SEQ * HDIM) return;
    int t = i >> 6;
    int d = i & 63;
    int fi = (d < 32) ? d : d - 32;
    float inv = powf(10000.0f, -((float)fi) / 32.0f);
    float ang = (float)t * inv;
    g_cos[i] = cosf(ang);
    g_sin[i] = sinf(ang);
}

// ---------------------------------------------------------------------------
// SGEMM: C[M,N] = A[M,K] @ B[K,N].  128x128 tile, 8x8 microtile, 256 threads.
// EPI=0: plain store to C.
// EPI=1: QKV epilogue — apply RoPE to q/k sections, scatter to g_Q/g_K/g_V
//        in [b,h,t,d] layout.
// EPI=2: like 0 but A is ignored and g_Y is used as the A matrix.
// ---------------------------------------------------------------------------
template <int EPI>
__global__ __launch_bounds__(256)
void gemm_kernel(const float* __restrict__ A, const float* __restrict__ B,
                 float* __restrict__ C, int M, int N, int K)
{
    __shared__ __align__(16) float As[16][132];   // [k][m], padded
    __shared__ __align__(16) float Bs[16][128];   // [k][n]

    const float* Aptr = (EPI == 2) ? g_Y : A;

    const int tid = threadIdx.x;
    const int tx  = tid & 15;     // n-dim, 16
    const int ty  = tid >> 4;     // m-dim, 16
    const int m0  = blockIdx.y * 128;
    const int n0  = blockIdx.x * 128;

    float acc[8][8];
    #pragma unroll
    for (int r = 0; r < 8; r++)
        #pragma unroll
        for (int c = 0; c < 8; c++) acc[r][c] = 0.0f;

    for (int k0 = 0; k0 < K; k0 += 16) {
        // Load A tile 128x16 (store transposed into As[k][m])
        #pragma unroll
        for (int l = 0; l < 2; l++) {
            int f   = tid + l * 256;           // 0..511
            int row = f >> 2;                  // 0..127
            int c4  = (f & 3) * 4;             // 0,4,8,12
            float4 v = *reinterpret_cast<const float4*>(
                Aptr + (size_t)(m0 + row) * K + k0 + c4);
            As[c4 + 0][row] = v.x;
            As[c4 + 1][row] = v.y;
            As[c4 + 2][row] = v.z;
            As[c4 + 3][row] = v.w;
        }
        // Load B tile 16x128
        #pragma unroll
        for (int l = 0; l < 2; l++) {
            int f   = tid + l * 256;
            int row = f >> 5;                  // 0..15
            int c4  = (f & 31) * 4;            // 0..124
            *reinterpret_cast<float4*>(&Bs[row][c4]) =
                *reinterpret_cast<const float4*>(
                    B + (size_t)(k0 + row) * N + n0 + c4);
        }
        __syncthreads();

        #pragma unroll
        for (int kk = 0; kk < 16; kk++) {
            float4 a0 = *reinterpret_cast<const float4*>(&As[kk][ty * 8]);
            float4 a1 = *reinterpret_cast<const float4*>(&As[kk][ty * 8 + 4]);
            float4 b0 = *reinterpret_cast<const float4*>(&Bs[kk][tx * 8]);
            float4 b1 = *reinterpret_cast<const float4*>(&Bs[kk][tx * 8 + 4]);
            float av[8] = {a0.x, a0.y, a0.z, a0.w, a1.x, a1.y, a1.z, a1.w};
            float bv[8] = {b0.x, b0.y, b0.z, b0.w, b1.x, b1.y, b1.z, b1.w};
            #pragma unroll
            for (int r = 0; r < 8; r++)
                #pragma unroll
                for (int c = 0; c < 8; c++)
                    acc[r][c] += av[r] * bv[c];
        }
        __syncthreads();
    }

    if (EPI == 0 || EPI == 2) {
        #pragma unroll
        for (int r = 0; r < 8; r++) {
            int m = m0 + ty * 8 + r;
            float* dst = C + (size_t)m * N + n0 + tx * 8;
            *reinterpret_cast<float4*>(dst) =
                make_float4(acc[r][0], acc[r][1], acc[r][2], acc[r][3]);
            *reinterpret_cast<float4*>(dst + 4) =
                make_float4(acc[r][4], acc[r][5], acc[r][6], acc[r][7]);
        }
    } else {
        // EPI == 1 : RoPE + scatter.  This thread's 8 columns lie inside one
        // q/k/v section and one head (8 | 64 | 1024 alignment).
        const int nb      = n0 + tx * 8;
        const int section = nb >> 10;          // 0=q, 1=k, 2=v
        const int within  = nb & 1023;
        const int h       = within >> 6;
        const int d0      = within & 63;

        #pragma unroll
        for (int r = 0; r < 8; r++) {
            int m  = m0 + ty * 8 + r;
            int bb = m >> 11;                  // / SEQ
            int t  = m & 2047;
            size_t base = ((size_t)(bb * NHEAD + h) * SEQ + t) * HDIM + d0;

            if (section == 2) {
                float* dst = g_V + base;
                *reinterpret_cast<float4*>(dst) =
                    make_float4(acc[r][0], acc[r][1], acc[r][2], acc[r][3]);
                *reinterpret_cast<float4*>(dst + 4) =
                    make_float4(acc[r][4], acc[r][5], acc[r][6], acc[r][7]);
            } else {
                float out[8];
                #pragma unroll
                for (int c = 0; c < 8; c += 2) {
                    int d = d0 + c;
                    int idx = t * HDIM + d;
                    float c0 = g_cos[idx],     s0 = g_sin[idx];
                    float c1 = g_cos[idx + 1], s1 = g_sin[idx + 1];
                    float e = acc[r][c], o = acc[r][c + 1];
                    out[c]     = e * c0 - o * s0;   // even: x*cos - x_odd*sin
                    out[c + 1] = o * c1 + e * s1;   // odd:  x*cos + x_even*sin
                }
                float* dst = ((section == 0) ? g_Q : g_K) + base;
                *reinterpret_cast<float4*>(dst) =
                    make_float4(out[0], out[1], out[2], out[3]);
                *reinterpret_cast<float4*>(dst + 4) =
                    make_float4(out[4], out[5], out[6], out[7]);
            }
        }
    }
}

// ---------------------------------------------------------------------------
// Flash attention: one CTA per (q-tile of 64, head, batch).
// 256 threads = 16x16; each thread owns a 4x4 microtile.
// Online softmax over 32 K-tiles of 64 rows.
// ---------------------------------------------------------------------------
#define ATT_PAD 65
#define ATT_SMEM (4 * 64 * ATT_PAD * 4)

__global__ __launch_bounds__(256)
void attn_kernel()
{
    extern __shared__ float sm[];
    float* Qs = sm;                    // [64][65]
    float* Ks = Qs + 64 * ATT_PAD;
    float* Vs = Ks + 64 * ATT_PAD;
    float* Ps = Vs + 64 * ATT_PAD;

    const int tid = threadIdx.x;
    const int tx  = tid & 15;
    const int ty  = tid >> 4;
    const int qt  = blockIdx.x;        // 0..31
    const int h   = blockIdx.y;        // 0..15
    const int bb  = blockIdx.z;        // 0..1

    const size_t head_base = (size_t)(bb * NHEAD + h) * SEQ * HDIM;

    // Load Q tile
    for (int i = tid; i < 64 * 64; i += 256) {
        int r = i >> 6, c = i & 63;
        Qs[r * ATT_PAD + c] = g_Q[head_base + (size_t)(qt * 64 + r) * HDIM + c];
    }

    float m_[4], l_[4], o[4][4];
    #pragma unroll
    for (int r = 0; r < 4; r++) {
        m_[r] = -INFINITY;
        l_[r] = 0.0f;
        #pragma unroll
        for (int c = 0; c < 4; c++) o[r][c] = 0.0f;
    }
    __syncthreads();

    for (int kt = 0; kt < SEQ / 64; kt++) {
        // Load K and V tiles
        for (int i = tid; i < 64 * 64; i += 256) {
            int r = i >> 6, c = i & 63;
            size_t g = head_base + (size_t)(kt * 64 + r) * HDIM + c;
            Ks[r * ATT_PAD + c] = g_K[g];
            Vs[r * ATT_PAD + c] = g_V[g];
        }
        __syncthreads();

        // S = Q @ K^T  (4x4 microtile)
        float s[4][4];
        #pragma unroll
        for (int r = 0; r < 4; r++)
            #pragma unroll
            for (int c = 0; c < 4; c++) s[r][c] = 0.0f;

        #pragma unroll 16
        for (int kk = 0; kk < 64; kk++) {
            float qv[4], kv[4];
            #pragma unroll
            for (int r = 0; r < 4; r++) qv[r] = Qs[(ty * 4 + r) * ATT_PAD + kk];
            #pragma unroll
            for (int c = 0; c < 4; c++) kv[c] = Ks[(tx * 4 + c) * ATT_PAD + kk];
            #pragma unroll
            for (int r = 0; r < 4; r++)
                #pragma unroll
                for (int c = 0; c < 4; c++)
                    s[r][c] += qv[r] * kv[c];
        }

        // Online softmax (row groups of 16 threads share one q-row set)
        const float scale = 0.125f;   // 1/sqrt(64)
        #pragma unroll
        for (int r = 0; r < 4; r++) {
            float mloc = -INFINITY;
            #pragma unroll
            for (int c = 0; c < 4; c++) {
                s[r][c] *= scale;
                mloc = fmaxf(mloc, s[r][c]);
            }
            #pragma unroll
            for (int off = 8; off >= 1; off >>= 1)
                mloc = fmaxf(mloc, __shfl_xor_sync(0xffffffffu, mloc, off));

            float mnew  = fmaxf(m_[r], mloc);
            float alpha = __expf(m_[r] - mnew);
            float psum  = 0.0f;
            #pragma unroll
            for (int c = 0; c < 4; c++) {
                float p = __expf(s[r][c] - mnew);
                s[r][c] = p;
                psum += p;
            }
            #pragma unroll
            for (int off = 8; off >= 1; off >>= 1)
                psum += __shfl_xor_sync(0xffffffffu, psum, off);

            l_[r] = l_[r] * alpha + psum;
            m_[r] = mnew;
            #pragma unroll
            for (int c = 0; c < 4; c++) o[r][c] *= alpha;
            #pragma unroll
            for (int c = 0; c < 4; c++)
                Ps[(ty * 4 + r) * ATT_PAD + tx * 4 + c] = s[r][c];
        }
        __syncthreads();

        // O += P @ V
        #pragma unroll 16
        for (int kk = 0; kk < 64; kk++) {
            float pv[4], vv[4];
            #pragma unroll
            for (int r = 0; r < 4; r++) pv[r] = Ps[(ty * 4 + r) * ATT_PAD + kk];
            #pragma unroll
            for (int c = 0; c < 4; c++) vv[c] = Vs[kk * ATT_PAD + tx * 4 + c];
            #pragma unroll
            for (int r = 0; r < 4; r++)
                #pragma unroll
                for (int c = 0; c < 4; c++)
                    o[r][c] += pv[r] * vv[c];
        }
        __syncthreads();
    }

    // Write out: y[b, t, h*64 + d]
    #pragma unroll
    for (int r = 0; r < 4; r++) {
        int t = qt * 64 + ty * 4 + r;
        float inv = 1.0f / l_[r];
        #pragma unroll
        for (int c = 0; c < 4; c++) {
            g_Y[((size_t)bb * SEQ + t) * DMODEL + h * HDIM + tx * 4 + c] =
                o[r][c] * inv;
        }
    }
}

// ---------------------------------------------------------------------------
extern "C" void kernel_launch(void* const* d_in, const int* in_sizes, int n_in,
                              void* d_out, int out_size)
{
    const float* x     = (const float*)d_in[0];
    const float* w_qkv = (const float*)d_in[1];
    const float* w_out = (const float*)d_in[2];
    float* out = (float*)d_out;

    // 1. RoPE table
    rope_table_kernel<<<(SEQ * HDIM + 255) / 256, 256>>>();

    // 2. QKV GEMM + fused RoPE/scatter epilogue
    gemm_kernel<1><<<dim3(N_QKV / 128, BT / 128), 256>>>(
        x, w_qkv, nullptr, BT, N_QKV, DMODEL);

    // 3. Attention
    cudaFuncSetAttribute(attn_kernel,
                         cudaFuncAttributeMaxDynamicSharedMemorySize, ATT_SMEM);
    attn_kernel<<<dim3(SEQ / 64, NHEAD, BATCH), 256, ATT_SMEM>>>();

    // 4. Output projection
    gemm_kernel<2><<<dim3(DMODEL / 128, BT / 128), 256>>>(
        nullptr, w_out, out, BT, DMODEL, DMODEL);
}

// round 3
// speedup vs baseline: 1.0267x; 1.0267x over previous
#include <cuda_runtime.h>
#include <cuda_bf16.h>
#include <math.h>

#define BATCH   2
#define SEQ     2048
#define DMODEL  1024
#define NHEAD   16
#define HDIM    64
#define BT      (BATCH * SEQ)          // 4096
#define N_QKV   (3 * DMODEL)           // 3072

__device__ float g_Q[BATCH * NHEAD * SEQ * HDIM];   // [b,h,t,d]
__device__ float g_K[BATCH * NHEAD * SEQ * HDIM];
__device__ float g_V[BATCH * NHEAD * SEQ * HDIM];
__device__ float g_Y[BT * DMODEL];
__device__ float g_cos[SEQ * HDIM];
__device__ float g_sin[SEQ * HDIM];

// ---------------------------------------------------------------------------
__global__ void rope_table_kernel() {
    int i = blockIdx.x * blockDim.x + threadIdx.x;
    if (i >= SEQ * HDIM) return;
    int t = i >> 6;
    int d = i & 63;
    int fi = (d < 32) ? d : d - 32;
    float inv = powf(10000.0f, -((float)fi) / 32.0f);
    float ang = (float)t * inv;
    g_cos[i] = cosf(ang);
    g_sin[i] = sinf(ang);
}

// ---------------------------------------------------------------------------
// Double-buffered SGEMM: 128x128 tile, BK=16, 8x8 microtile, 256 threads.
// EPI=0 plain, EPI=1 QKV(RoPE+scatter), EPI=2 A:=g_Y.
// ---------------------------------------------------------------------------
template <int EPI>
__global__ __launch_bounds__(256, 2)
void gemm_kernel(const float* __restrict__ A, const float* __restrict__ B,
                 float* __restrict__ C, int M, int N, int K)
{
    __shared__ __align__(16) float As[2][16][132];   // [k][m]
    __shared__ __align__(16) float Bs[2][16][128];   // [k][n]

    const float* Aptr = (EPI == 2) ? g_Y : A;

    const int tid = threadIdx.x;
    const int tx  = tid & 15;
    const int ty  = tid >> 4;
    const int m0  = blockIdx.y * 128;
    const int n0  = blockIdx.x * 128;

    // staging regs for the next tile
    float4 ra[2], rb[2];

    const int a_row0 = (tid) >> 2,        a_c4 = (tid & 3) * 4;
    const int a_row1 = (tid + 256) >> 2;
    const int b_row0 = (tid) >> 5,        b_c4 = (tid & 31) * 4;
    const int b_row1 = (tid + 256) >> 5;

    #define GEMM_LDG(k0)                                                          \
        ra[0] = *reinterpret_cast<const float4*>(Aptr + (size_t)(m0 + a_row0) * K + (k0) + a_c4); \
        ra[1] = *reinterpret_cast<const float4*>(Aptr + (size_t)(m0 + a_row1) * K + (k0) + a_c4); \
        rb[0] = *reinterpret_cast<const float4*>(B + (size_t)((k0) + b_row0) * N + n0 + b_c4);    \
        rb[1] = *reinterpret_cast<const float4*>(B + (size_t)((k0) + b_row1) * N + n0 + b_c4);

    #define GEMM_STS(buf)                                                         \
        As[buf][a_c4 + 0][a_row0] = ra[0].x;                                      \
        As[buf][a_c4 + 1][a_row0] = ra[0].y;                                      \
        As[buf][a_c4 + 2][a_row0] = ra[0].z;                                      \
        As[buf][a_c4 + 3][a_row0] = ra[0].w;                                      \
        As[buf][a_c4 + 0][a_row1] = ra[1].x;                                      \
        As[buf][a_c4 + 1][a_row1] = ra[1].y;                                      \
        As[buf][a_c4 + 2][a_row1] = ra[1].z;                                      \
        As[buf][a_c4 + 3][a_row1] = ra[1].w;                                      \
        *reinterpret_cast<float4*>(&Bs[buf][b_row0][b_c4]) = rb[0];               \
        *reinterpret_cast<float4*>(&Bs[buf][b_row1][b_c4]) = rb[1];

    float acc[8][8];
    #pragma unroll
    for (int r = 0; r < 8; r++)
        #pragma unroll
        for (int c = 0; c < 8; c++) acc[r][c] = 0.0f;

    GEMM_LDG(0);
    GEMM_STS(0);
    __syncthreads();

    const int nk = K >> 4;
    for (int kt = 0; kt < nk; kt++) {
        const int buf = kt & 1;
        if (kt + 1 < nk) { GEMM_LDG((kt + 1) << 4); }

        #pragma unroll
        for (int kk = 0; kk < 16; kk++) {
            float4 a0 = *reinterpret_cast<const float4*>(&As[buf][kk][ty * 8]);
            float4 a1 = *reinterpret_cast<const float4*>(&As[buf][kk][ty * 8 + 4]);
            float4 b0 = *reinterpret_cast<const float4*>(&Bs[buf][kk][tx * 8]);
            float4 b1 = *reinterpret_cast<const float4*>(&Bs[buf][kk][tx * 8 + 4]);
            float av[8] = {a0.x, a0.y, a0.z, a0.w, a1.x, a1.y, a1.z, a1.w};
            float bv[8] = {b0.x, b0.y, b0.z, b0.w, b1.x, b1.y, b1.z, b1.w};
            #pragma unroll
            for (int r = 0; r < 8; r++)
                #pragma unroll
                for (int c = 0; c < 8; c++)
                    acc[r][c] += av[r] * bv[c];
        }

        if (kt + 1 < nk) { GEMM_STS(buf ^ 1); }
        __syncthreads();
    }

    if (EPI == 0 || EPI == 2) {
        #pragma unroll
        for (int r = 0; r < 8; r++) {
            int m = m0 + ty * 8 + r;
            float* dst = C + (size_t)m * N + n0 + tx * 8;
            *reinterpret_cast<float4*>(dst) =
                make_float4(acc[r][0], acc[r][1], acc[r][2], acc[r][3]);
            *reinterpret_cast<float4*>(dst + 4) =
                make_float4(acc[r][4], acc[r][5], acc[r][6], acc[r][7]);
        }
    } else {
        const int nb      = n0 + tx * 8;
        const int section = nb >> 10;
        const int within  = nb & 1023;
        const int h       = within >> 6;
        const int d0      = within & 63;

        #pragma unroll
        for (int r = 0; r < 8; r++) {
            int m  = m0 + ty * 8 + r;
            int bb = m >> 11;
            int t  = m & 2047;
            size_t base = ((size_t)(bb * NHEAD + h) * SEQ + t) * HDIM + d0;

            if (section == 2) {
                float* dst = g_V + base;
                *reinterpret_cast<float4*>(dst) =
                    make_float4(acc[r][0], acc[r][1], acc[r][2], acc[r][3]);
                *reinterpret_cast<float4*>(dst + 4) =
                    make_float4(acc[r][4], acc[r][5], acc[r][6], acc[r][7]);
            } else {
                float out[8];
                #pragma unroll
                for (int c = 0; c < 8; c += 2) {
                    int d = d0 + c;
                    int idx = t * HDIM + d;
                    float c0 = g_cos[idx],     s0 = g_sin[idx];
                    float c1 = g_cos[idx + 1], s1 = g_sin[idx + 1];
                    float e = acc[r][c], o = acc[r][c + 1];
                    out[c]     = e * c0 - o * s0;
                    out[c + 1] = o * c1 + e * s1;
                }
                float* dst = ((section == 0) ? g_Q : g_K) + base;
                *reinterpret_cast<float4*>(dst) =
                    make_float4(out[0], out[1], out[2], out[3]);
                *reinterpret_cast<float4*>(dst + 4) =
                    make_float4(out[4], out[5], out[6], out[7]);
            }
        }
    }
    #undef GEMM_LDG
    #undef GEMM_STS
}

// ---------------------------------------------------------------------------
// Flash attention v2: Q-tile 128, K-tile 128, 256 threads.
// S: 8x8 microtile (balanced 4 FMA/float). P stored TRANSPOSED so the P@V
// loop reads contiguous float4s. Softmax scale folded into Q load.
// smem: QsT[64][132] + KsT[64][132] + Vs[128][68] + PsT[128][132] = 166KB.
// ---------------------------------------------------------------------------
#define QT_PAD 132
#define V_PAD  68
#define ATT_SMEM ((2 * 64 * QT_PAD + 128 * V_PAD + 128 * QT_PAD) * 4)

__global__ __launch_bounds__(256, 1)
void attn_kernel()
{
    extern __shared__ float sm[];
    float* QsT = sm;                          // [64][132]  (d, qrow)
    float* KsT = QsT + 64 * QT_PAD;           // [64][132]  (d, kcol)
    float* Vs  = KsT + 64 * QT_PAD;           // [128][68]  (krow, d)
    float* PsT = Vs  + 128 * V_PAD;           // [128][132] (kcol, qrow)

    const int tid = threadIdx.x;
    const int tx  = tid & 15;
    const int ty  = tid >> 4;
    const int qt  = blockIdx.x;               // 0..15
    const int h   = blockIdx.y;
    const int bb  = blockIdx.z;

    const size_t head_base = (size_t)(bb * NHEAD + h) * SEQ * HDIM;

    // ---- load Q tile (128x64), scale by 1/8, transpose into QsT ----
    {
        const float* src = g_Q + head_base + (size_t)qt * 128 * HDIM;
        #pragma unroll
        for (int i = 0; i < 8; i++) {
            int f   = tid + i * 256;          // 0..2047
            int row = f >> 4;                 // 0..127
            int c4  = (f & 15) * 4;
            float4 v = *reinterpret_cast<const float4*>(src + row * HDIM + c4);
            float comp[4] = {v.x * 0.125f, v.y * 0.125f, v.z * 0.125f, v.w * 0.125f};
            #pragma unroll
            for (int jj = 0; jj < 4; jj++) {
                int j = (jj + tx) & 3;        // lane-rotated scatter (cuts conflicts)
                QsT[(c4 + j) * QT_PAD + row] = comp[j];
            }
        }
    }

    float m_[8], l_[8], o[8][4];
    #pragma unroll
    for (int r = 0; r < 8; r++) {
        m_[r] = -INFINITY;
        l_[r] = 0.0f;
        #pragma unroll
        for (int c = 0; c < 4; c++) o[r][c] = 0.0f;
    }

    for (int kt = 0; kt < SEQ / 128; kt++) {
        // ---- load K (transposed) and V tiles ----
        {
            const float* ksrc = g_K + head_base + (size_t)kt * 128 * HDIM;
            const float* vsrc = g_V + head_base + (size_t)kt * 128 * HDIM;
            #pragma unroll
            for (int i = 0; i < 8; i++) {
                int f   = tid + i * 256;
                int row = f >> 4;
                int c4  = (f & 15) * 4;
                float4 kv = *reinterpret_cast<const float4*>(ksrc + row * HDIM + c4);
                float kc[4] = {kv.x, kv.y, kv.z, kv.w};
                #pragma unroll
                for (int jj = 0; jj < 4; jj++) {
                    int j = (jj + tx) & 3;
                    KsT[(c4 + j) * QT_PAD + row] = kc[j];
                }
                float4 vv = *reinterpret_cast<const float4*>(vsrc + row * HDIM + c4);
                *reinterpret_cast<float4*>(&Vs[row * V_PAD + c4]) = vv;
            }
        }
        __syncthreads();

        // ---- S = (Q*scale) @ K^T : 8x8 microtile ----
        float s[8][8];
        #pragma unroll
        for (int r = 0; r < 8; r++)
            #pragma unroll
            for (int c = 0; c < 8; c++) s[r][c] = 0.0f;

        #pragma unroll 8
        for (int kk = 0; kk < 64; kk++) {
            float4 a0 = *reinterpret_cast<const float4*>(&QsT[kk * QT_PAD + ty * 8]);
            float4 a1 = *reinterpret_cast<const float4*>(&QsT[kk * QT_PAD + ty * 8 + 4]);
            float4 b0 = *reinterpret_cast<const float4*>(&KsT[kk * QT_PAD + tx * 8]);
            float4 b1 = *reinterpret_cast<const float4*>(&KsT[kk * QT_PAD + tx * 8 + 4]);
            float av[8] = {a0.x, a0.y, a0.z, a0.w, a1.x, a1.y, a1.z, a1.w};
            float bv[8] = {b0.x, b0.y, b0.z, b0.w, b1.x, b1.y, b1.z, b1.w};
            #pragma unroll
            for (int r = 0; r < 8; r++)
                #pragma unroll
                for (int c = 0; c < 8; c++)
                    s[r][c] += av[r] * bv[c];
        }

        // ---- online softmax per row (rows shared across 16 tx lanes) ----
        #pragma unroll
        for (int r = 0; r < 8; r++) {
            float mloc = s[r][0];
            #pragma unroll
            for (int c = 1; c < 8; c++) mloc = fmaxf(mloc, s[r][c]);
            #pragma unroll
            for (int off = 8; off >= 1; off >>= 1)
                mloc = fmaxf(mloc, __shfl_xor_sync(0xffffffffu, mloc, off));

            float mnew  = fmaxf(m_[r], mloc);
            float alpha = __expf(m_[r] - mnew);
            float psum  = 0.0f;
            #pragma unroll
            for (int c = 0; c < 8; c++) {
                float p = __expf(s[r][c] - mnew);
                s[r][c] = p;
                psum += p;
            }
            #pragma unroll
            for (int off = 8; off >= 1; off >>= 1)
                psum += __shfl_xor_sync(0xffffffffu, psum, off);

            l_[r] = l_[r] * alpha + psum;
            m_[r] = mnew;
            #pragma unroll
            for (int c = 0; c < 4; c++) o[r][c] *= alpha;
        }

        // ---- write P transposed: PsT[kcol][qrow] ----
        #pragma unroll
        for (int c = 0; c < 8; c++) {
            int col = tx * 8 + c;
            *reinterpret_cast<float4*>(&PsT[col * QT_PAD + ty * 8]) =
                make_float4(s[0][c], s[1][c], s[2][c], s[3][c]);
            *reinterpret_cast<float4*>(&PsT[col * QT_PAD + ty * 8 + 4]) =
                make_float4(s[4][c], s[5][c], s[6][c], s[7][c]);
        }
        __syncthreads();

        // ---- O += P @ V : 8x4 microtile, contiguous reads ----
        #pragma unroll 8
        for (int kk = 0; kk < 128; kk++) {
            float4 p0 = *reinterpret_cast<const float4*>(&PsT[kk * QT_PAD + ty * 8]);
            float4 p1 = *reinterpret_cast<const float4*>(&PsT[kk * QT_PAD + ty * 8 + 4]);
            float4 vv = *reinterpret_cast<const float4*>(&Vs[kk * V_PAD + tx * 4]);
            float pv[8] = {p0.x, p0.y, p0.z, p0.w, p1.x, p1.y, p1.z, p1.w};
            #pragma unroll
            for (int r = 0; r < 8; r++) {
                o[r][0] += pv[r] * vv.x;
                o[r][1] += pv[r] * vv.y;
                o[r][2] += pv[r] * vv.z;
                o[r][3] += pv[r] * vv.w;
            }
        }
        __syncthreads();
    }

    // ---- epilogue ----
    #pragma unroll
    for (int r = 0; r < 8; r++) {
        int t = qt * 128 + ty * 8 + r;
        float inv = 1.0f / l_[r];
        float* dst = g_Y + ((size_t)bb * SEQ + t) * DMODEL + h * HDIM + tx * 4;
        *reinterpret_cast<float4*>(dst) =
            make_float4(o[r][0] * inv, o[r][1] * inv, o[r][2] * inv, o[r][3] * inv);
    }
}

// ---------------------------------------------------------------------------
extern "C" void kernel_launch(void* const* d_in, const int* in_sizes, int n_in,
                              void* d_out, int out_size)
{
    const float* x     = (const float*)d_in[0];
    const float* w_qkv = (const float*)d_in[1];
    const float* w_out = (const float*)d_in[2];
    float* out = (float*)d_out;

    rope_table_kernel<<<(SEQ * HDIM + 255) / 256, 256>>>();

    gemm_kernel<1><<<dim3(N_QKV / 128, BT / 128), 256>>>(
        x, w_qkv, nullptr, BT, N_QKV, DMODEL);

    cudaFuncSetAttribute(attn_kernel,
                         cudaFuncAttributeMaxDynamicSharedMemorySize, ATT_SMEM);
    attn_kernel<<<dim3(SEQ / 128, NHEAD, BATCH), 256, ATT_SMEM>>>();

    gemm_kernel<2><<<dim3(DMODEL / 128, BT / 128), 256>>>(
        nullptr, w_out, out, BT, DMODEL, DMODEL);
}

// round 5
// speedup vs baseline: 1.3857x; 1.3497x over previous
#include <cuda_runtime.h>
#include <cuda_bf16.h>
#include <math.h>
#include <stdint.h>

#define BATCH   2
#define SEQ     2048
#define DMODEL  1024
#define NHEAD   16
#define HDIM    64
#define BT      (BATCH * SEQ)          // 4096
#define N_QKV   (3 * DMODEL)           // 3072

// fp32 intermediates
__device__ float g_Q[BATCH * NHEAD * SEQ * HDIM];   // [b,h,t,d]
__device__ float g_K[BATCH * NHEAD * SEQ * HDIM];
__device__ float g_V[BATCH * NHEAD * SEQ * HDIM];
__device__ float g_Y[BT * DMODEL];
__device__ float g_cos[SEQ * HDIM];
__device__ float g_sin[SEQ * HDIM];

// split-bf16 scratch
__device__ __nv_bfloat16 g_xh[BT * DMODEL];
__device__ __nv_bfloat16 g_xl[BT * DMODEL];
__device__ __nv_bfloat16 g_yh[BT * DMODEL];
__device__ __nv_bfloat16 g_yl[BT * DMODEL];
__device__ __nv_bfloat16 g_wqh[N_QKV * DMODEL];     // transposed [n][k]
__device__ __nv_bfloat16 g_wql[N_QKV * DMODEL];
__device__ __nv_bfloat16 g_woh[DMODEL * DMODEL];    // transposed [n][k]
__device__ __nv_bfloat16 g_wol[DMODEL * DMODEL];

// ---------------------------------------------------------------------------
__device__ __forceinline__ void split2(float v, __nv_bfloat16& h, __nv_bfloat16& l) {
    h = __float2bfloat16(v);
    l = __float2bfloat16(v - __bfloat162float(h));
}

__global__ void rope_table_kernel() {
    int i = blockIdx.x * blockDim.x + threadIdx.x;
    if (i >= SEQ * HDIM) return;
    int t = i >> 6;
    int d = i & 63;
    int fi = (d < 32) ? d : d - 32;
    float inv = powf(10000.0f, -((float)fi) / 32.0f);
    float ang = (float)t * inv;
    g_cos[i] = cosf(ang);
    g_sin[i] = sinf(ang);
}

// elementwise split: in fp32 [n] -> hi/lo bf16
__global__ void split_kernel(const float* __restrict__ in,
                             __nv_bfloat16* __restrict__ hi,
                             __nv_bfloat16* __restrict__ lo, int n)
{
    int i = (blockIdx.x * blockDim.x + threadIdx.x) * 4;
    if (i >= n) return;
    float4 v = *reinterpret_cast<const float4*>(in + i);
    __nv_bfloat16 h[4], l[4];
    split2(v.x, h[0], l[0]); split2(v.y, h[1], l[1]);
    split2(v.z, h[2], l[2]); split2(v.w, h[3], l[3]);
    *reinterpret_cast<uint2*>(hi + i) = *reinterpret_cast<uint2*>(h);
    *reinterpret_cast<uint2*>(lo + i) = *reinterpret_cast<uint2*>(l);
}

// transpose + split: W[K][N] fp32 -> Wt_h/Wt_l [N][K] bf16
__global__ void tsplit_kernel(const float* __restrict__ W,
                              __nv_bfloat16* __restrict__ th,
                              __nv_bfloat16* __restrict__ tl, int K, int N)
{
    __shared__ float tile[32][33];
    const int n0 = blockIdx.x * 32;
    const int k0 = blockIdx.y * 32;
    const int tx = threadIdx.x, ty = threadIdx.y;
    #pragma unroll
    for (int j = 0; j < 4; j++)
        tile[ty + j * 8][tx] = W[(size_t)(k0 + ty + j * 8) * N + n0 + tx];
    __syncthreads();
    #pragma unroll
    for (int j = 0; j < 4; j++) {
        float v = tile[tx][ty + j * 8];
        __nv_bfloat16 h, l;
        split2(v, h, l);
        size_t o = (size_t)(n0 + ty + j * 8) * K + k0 + tx;
        th[o] = h;
        tl[o] = l;
    }
}

// ===========================================================================
// mma.sync split-bf16 GEMM.  C[M,N] = A[M,K] @ Bt[N,K]^T  (fp32-equivalent)
// CTA 128x128, K-chunk 32, 256 threads (8 warps, warp tile 64x32).
// cp.async double-buffered.  D += Ah*Bh + Ah*Bl + Al*Bh.
// EPI=1: RoPE+scatter to g_Q/g_K/g_V.   EPI=2: plain store to C.
// ===========================================================================
#define ROWB   80                       // padded row stride bytes (40 bf16)
#define ARRB   (128 * ROWB)             // one tile array: 10240 B
#define STAGEB (4 * ARRB)               // Ah,Al,Bh,Bl
#define GEMM_SMEM (2 * STAGEB)          // 81920 B

#define CP16(dst, src) \
    asm volatile("cp.async.cg.shared.global [%0], [%1], 16;" \
                 :: "r"(dst), "l"(src))
#define CP_COMMIT() asm volatile("cp.async.commit_group;")
#define CP_WAIT1()  asm volatile("cp.async.wait_group 1;")
#define CP_WAIT0()  asm volatile("cp.async.wait_group 0;")

__device__ __forceinline__ void mma16816(float* c, const uint32_t* a, const uint32_t* b) {
    asm volatile(
        "mma.sync.aligned.m16n8k16.row.col.f32.bf16.bf16.f32 "
        "{%0,%1,%2,%3}, {%4,%5,%6,%7}, {%8,%9}, {%0,%1,%2,%3};"
        : "+f"(c[0]), "+f"(c[1]), "+f"(c[2]), "+f"(c[3])
        : "r"(a[0]), "r"(a[1]), "r"(a[2]), "r"(a[3]), "r"(b[0]), "r"(b[1]));
}

template <int EPI>
__global__ __launch_bounds__(256, 1)
void mma_gemm_kernel(const __nv_bfloat16* __restrict__ Ah_g,
                     const __nv_bfloat16* __restrict__ Al_g,
                     const __nv_bfloat16* __restrict__ Bh_g,
                     const __nv_bfloat16* __restrict__ Bl_g,
                     float* __restrict__ C, int M, int N, int K)
{
    extern __shared__ char smc[];
    const uint32_t smem_u32 = (uint32_t)__cvta_generic_to_shared(smc);

    const int tid  = threadIdx.x;
    const int lane = tid & 31;
    const int wid  = tid >> 5;
    const int wm   = wid & 1;            // 0..1  (64-row half)
    const int wn   = wid >> 1;           // 0..3  (32-col quarter)
    const int g    = lane >> 2;          // 0..7
    const int t    = lane & 3;           // 0..3
    const int m0   = blockIdx.y * 128;
    const int n0   = blockIdx.x * 128;

    // cp.async source/dest indexing: 2 segments of 16B per row-array per thread
    const int ld_row = tid >> 2;         // 0..63   (two iters cover 128 rows)
    const int ld_seg = tid & 3;          // 16B segment (seg*8 bf16)

    float acc[4][4][4];
    #pragma unroll
    for (int a = 0; a < 4; a++)
        #pragma unroll
        for (int b = 0; b < 4; b++)
            #pragma unroll
            for (int c = 0; c < 4; c++) acc[a][b][c] = 0.0f;

    #define LOAD_STAGE(kt, s) do {                                            \
        uint32_t sb = smem_u32 + (s) * STAGEB;                                \
        _Pragma("unroll")                                                     \
        for (int i = 0; i < 2; i++) {                                         \
            int row = ld_row + i * 64;                                        \
            uint32_t so = sb + row * ROWB + ld_seg * 16;                      \
            size_t  ga = (size_t)(m0 + row) * K + (kt) * 32 + ld_seg * 8;     \
            size_t  gb = (size_t)(n0 + row) * K + (kt) * 32 + ld_seg * 8;     \
            CP16(so,            Ah_g + ga);                                   \
            CP16(so + ARRB,     Al_g + ga);                                   \
            CP16(so + 2 * ARRB, Bh_g + gb);                                   \
            CP16(so + 3 * ARRB, Bl_g + gb);                                   \
        }                                                                     \
    } while (0)

    const int nk = K >> 5;               // chunks of 32
    LOAD_STAGE(0, 0);
    CP_COMMIT();

    for (int kt = 0; kt < nk; kt++) {
        const int s = kt & 1;
        if (kt + 1 < nk) {
            LOAD_STAGE(kt + 1, s ^ 1);
            CP_COMMIT();
            CP_WAIT1();
        } else {
            CP_WAIT0();
        }
        __syncthreads();

        const char* st = smc + s * STAGEB;
        const char* pAh = st;
        const char* pAl = st + ARRB;
        const char* pBh = st + 2 * ARRB;
        const char* pBl = st + 3 * ARRB;

        #pragma unroll
        for (int ks = 0; ks < 2; ks++) {
            const int kb = ks * 32;      // byte offset of k-step (16 elems)
            uint32_t af_h[4][4], af_l[4][4], bf_h[4][2], bf_l[4][2];
            #pragma unroll
            for (int mt = 0; mt < 4; mt++) {
                int off = (wm * 64 + mt * 16 + g) * ROWB + kb + t * 4;
                af_h[mt][0] = *(const uint32_t*)(pAh + off);
                af_h[mt][1] = *(const uint32_t*)(pAh + off + 8 * ROWB);
                af_h[mt][2] = *(const uint32_t*)(pAh + off + 16);
                af_h[mt][3] = *(const uint32_t*)(pAh + off + 8 * ROWB + 16);
                af_l[mt][0] = *(const uint32_t*)(pAl + off);
                af_l[mt][1] = *(const uint32_t*)(pAl + off + 8 * ROWB);
                af_l[mt][2] = *(const uint32_t*)(pAl + off + 16);
                af_l[mt][3] = *(const uint32_t*)(pAl + off + 8 * ROWB + 16);
            }
            #pragma unroll
            for (int nt = 0; nt < 4; nt++) {
                int off = (wn * 32 + nt * 8 + g) * ROWB + kb + t * 4;
                bf_h[nt][0] = *(const uint32_t*)(pBh + off);
                bf_h[nt][1] = *(const uint32_t*)(pBh + off + 16);
                bf_l[nt][0] = *(const uint32_t*)(pBl + off);
                bf_l[nt][1] = *(const uint32_t*)(pBl + off + 16);
            }
            #pragma unroll
            for (int mt = 0; mt < 4; mt++)
                #pragma unroll
                for (int nt = 0; nt < 4; nt++) {
                    mma16816(acc[mt][nt], af_h[mt], bf_h[nt]);
                    mma16816(acc[mt][nt], af_h[mt], bf_l[nt]);
                    mma16816(acc[mt][nt], af_l[mt], bf_h[nt]);
                }
        }
        __syncthreads();
    }
    #undef LOAD_STAGE

    // ---- epilogue: C fragment (g,2t),(g,2t+1),(g+8,2t),(g+8,2t+1) ----
    #pragma unroll
    for (int mt = 0; mt < 4; mt++) {
        const int mr0 = m0 + wm * 64 + mt * 16 + g;
        #pragma unroll
        for (int nt = 0; nt < 4; nt++) {
            const int col = n0 + wn * 32 + nt * 8 + 2 * t;
            const float* a = acc[mt][nt];
            if (EPI == 2) {
                *reinterpret_cast<float2*>(C + (size_t)mr0 * N + col) =
                    make_float2(a[0], a[1]);
                *reinterpret_cast<float2*>(C + (size_t)(mr0 + 8) * N + col) =
                    make_float2(a[2], a[3]);
            } else {
                const int section = col >> 10;
                const int within  = col & 1023;
                const int h       = within >> 6;
                const int d       = within & 63;      // even
                #pragma unroll
                for (int rr = 0; rr < 2; rr++) {
                    const int m  = mr0 + rr * 8;
                    const int bb = m >> 11;
                    const int tt = m & 2047;
                    size_t base = ((size_t)(bb * NHEAD + h) * SEQ + tt) * HDIM + d;
                    float e = a[rr * 2 + 0], o = a[rr * 2 + 1];
                    if (section == 2) {
                        *reinterpret_cast<float2*>(g_V + base) = make_float2(e, o);
                    } else {
                        int idx = tt * HDIM + d;
                        float c0 = g_cos[idx],     s0 = g_sin[idx];
                        float c1 = g_cos[idx + 1], s1 = g_sin[idx + 1];
                        float* dst = (section == 0) ? g_Q : g_K;
                        *reinterpret_cast<float2*>(dst + base) =
                            make_float2(e * c0 - o * s0, o * c1 + e * s1);
                    }
                }
            }
        }
    }
}

// ---------------------------------------------------------------------------
// Flash attention (SIMT, unchanged from best passing version)
// ---------------------------------------------------------------------------
#define QT_PAD 132
#define V_PAD  68
#define ATT_SMEM ((2 * 64 * QT_PAD + 128 * V_PAD + 128 * QT_PAD) * 4)

__global__ __launch_bounds__(256, 1)
void attn_kernel()
{
    extern __shared__ float smf[];
    float* QsT = smf;
    float* KsT = QsT + 64 * QT_PAD;
    float* Vs  = KsT + 64 * QT_PAD;
    float* PsT = Vs  + 128 * V_PAD;

    const int tid = threadIdx.x;
    const int tx  = tid & 15;
    const int ty  = tid >> 4;
    const int qt  = blockIdx.x;
    const int h   = blockIdx.y;
    const int bb  = blockIdx.z;

    const size_t head_base = (size_t)(bb * NHEAD + h) * SEQ * HDIM;

    {
        const float* src = g_Q + head_base + (size_t)qt * 128 * HDIM;
        #pragma unroll
        for (int i = 0; i < 8; i++) {
            int f   = tid + i * 256;
            int row = f >> 4;
            int c4  = (f & 15) * 4;
            float4 v = *reinterpret_cast<const float4*>(src + row * HDIM + c4);
            float comp[4] = {v.x * 0.125f, v.y * 0.125f, v.z * 0.125f, v.w * 0.125f};
            #pragma unroll
            for (int jj = 0; jj < 4; jj++) {
                int j = (jj + tx) & 3;
                QsT[(c4 + j) * QT_PAD + row] = comp[j];
            }
        }
    }

    float m_[8], l_[8], o[8][4];
    #pragma unroll
    for (int r = 0; r < 8; r++) {
        m_[r] = -INFINITY;
        l_[r] = 0.0f;
        #pragma unroll
        for (int c = 0; c < 4; c++) o[r][c] = 0.0f;
    }

    for (int kt = 0; kt < SEQ / 128; kt++) {
        {
            const float* ksrc = g_K + head_base + (size_t)kt * 128 * HDIM;
            const float* vsrc = g_V + head_base + (size_t)kt * 128 * HDIM;
            #pragma unroll
            for (int i = 0; i < 8; i++) {
                int f   = tid + i * 256;
                int row = f >> 4;
                int c4  = (f & 15) * 4;
                float4 kv = *reinterpret_cast<const float4*>(ksrc + row * HDIM + c4);
                float kc[4] = {kv.x, kv.y, kv.z, kv.w};
                #pragma unroll
                for (int jj = 0; jj < 4; jj++) {
                    int j = (jj + tx) & 3;
                    KsT[(c4 + j) * QT_PAD + row] = kc[j];
                }
                float4 vv = *reinterpret_cast<const float4*>(vsrc + row * HDIM + c4);
                *reinterpret_cast<float4*>(&Vs[row * V_PAD + c4]) = vv;
            }
        }
        __syncthreads();

        float s[8][8];
        #pragma unroll
        for (int r = 0; r < 8; r++)
            #pragma unroll
            for (int c = 0; c < 8; c++) s[r][c] = 0.0f;

        #pragma unroll 8
        for (int kk = 0; kk < 64; kk++) {
            float4 a0 = *reinterpret_cast<const float4*>(&QsT[kk * QT_PAD + ty * 8]);
            float4 a1 = *reinterpret_cast<const float4*>(&QsT[kk * QT_PAD + ty * 8 + 4]);
            float4 b0 = *reinterpret_cast<const float4*>(&KsT[kk * QT_PAD + tx * 8]);
            float4 b1 = *reinterpret_cast<const float4*>(&KsT[kk * QT_PAD + tx * 8 + 4]);
            float av[8] = {a0.x, a0.y, a0.z, a0.w, a1.x, a1.y, a1.z, a1.w};
            float bv[8] = {b0.x, b0.y, b0.z, b0.w, b1.x, b1.y, b1.z, b1.w};
            #pragma unroll
            for (int r = 0; r < 8; r++)
                #pragma unroll
                for (int c = 0; c < 8; c++)
                    s[r][c] += av[r] * bv[c];
        }

        #pragma unroll
        for (int r = 0; r < 8; r++) {
            float mloc = s[r][0];
            #pragma unroll
            for (int c = 1; c < 8; c++) mloc = fmaxf(mloc, s[r][c]);
            #pragma unroll
            for (int off = 8; off >= 1; off >>= 1)
                mloc = fmaxf(mloc, __shfl_xor_sync(0xffffffffu, mloc, off));

            float mnew  = fmaxf(m_[r], mloc);
            float alpha = __expf(m_[r] - mnew);
            float psum  = 0.0f;
            #pragma unroll
            for (int c = 0; c < 8; c++) {
                float p = __expf(s[r][c] - mnew);
                s[r][c] = p;
                psum += p;
            }
            #pragma unroll
            for (int off = 8; off >= 1; off >>= 1)
                psum += __shfl_xor_sync(0xffffffffu, psum, off);

            l_[r] = l_[r] * alpha + psum;
            m_[r] = mnew;
            #pragma unroll
            for (int c = 0; c < 4; c++) o[r][c] *= alpha;
        }

        #pragma unroll
        for (int c = 0; c < 8; c++) {
            int col = tx * 8 + c;
            *reinterpret_cast<float4*>(&PsT[col * QT_PAD + ty * 8]) =
                make_float4(s[0][c], s[1][c], s[2][c], s[3][c]);
            *reinterpret_cast<float4*>(&PsT[col * QT_PAD + ty * 8 + 4]) =
                make_float4(s[4][c], s[5][c], s[6][c], s[7][c]);
        }
        __syncthreads();

        #pragma unroll 8
        for (int kk = 0; kk < 128; kk++) {
            float4 p0 = *reinterpret_cast<const float4*>(&PsT[kk * QT_PAD + ty * 8]);
            float4 p1 = *reinterpret_cast<const float4*>(&PsT[kk * QT_PAD + ty * 8 + 4]);
            float4 vv = *reinterpret_cast<const float4*>(&Vs[kk * V_PAD + tx * 4]);
            float pv[8] = {p0.x, p0.y, p0.z, p0.w, p1.x, p1.y, p1.z, p1.w};
            #pragma unroll
            for (int r = 0; r < 8; r++) {
                o[r][0] += pv[r] * vv.x;
                o[r][1] += pv[r] * vv.y;
                o[r][2] += pv[r] * vv.z;
                o[r][3] += pv[r] * vv.w;
            }
        }
        __syncthreads();
    }

    #pragma unroll
    for (int r = 0; r < 8; r++) {
        int t = qt * 128 + ty * 8 + r;
        float inv = 1.0f / l_[r];
        float* dst = g_Y + ((size_t)bb * SEQ + t) * DMODEL + h * HDIM + tx * 4;
        *reinterpret_cast<float4*>(dst) =
            make_float4(o[r][0] * inv, o[r][1] * inv, o[r][2] * inv, o[r][3] * inv);
    }
}

// ---------------------------------------------------------------------------
static float* dev_addr_f(const void* sym) {
    void* p = nullptr;
    cudaGetSymbolAddress(&p, sym);
    return (float*)p;
}

extern "C" void kernel_launch(void* const* d_in, const int* in_sizes, int n_in,
                              void* d_out, int out_size)
{
    const float* x     = (const float*)d_in[0];
    const float* w_qkv = (const float*)d_in[1];
    const float* w_out = (const float*)d_in[2];
    float* out = (float*)d_out;

    static bool attr_done = false;
    if (!attr_done) {
        cudaFuncSetAttribute(mma_gemm_kernel<1>,
                             cudaFuncAttributeMaxDynamicSharedMemorySize, GEMM_SMEM);
        cudaFuncSetAttribute(mma_gemm_kernel<2>,
                             cudaFuncAttributeMaxDynamicSharedMemorySize, GEMM_SMEM);
        cudaFuncSetAttribute(attn_kernel,
                             cudaFuncAttributeMaxDynamicSharedMemorySize, ATT_SMEM);
        attr_done = true;
    }

    __nv_bfloat16 *xh, *xl, *yh, *yl, *wqh, *wql, *woh, *wol;
    cudaGetSymbolAddress((void**)&xh,  g_xh);
    cudaGetSymbolAddress((void**)&xl,  g_xl);
    cudaGetSymbolAddress((void**)&yh,  g_yh);
    cudaGetSymbolAddress((void**)&yl,  g_yl);
    cudaGetSymbolAddress((void**)&wqh, g_wqh);
    cudaGetSymbolAddress((void**)&wql, g_wql);
    cudaGetSymbolAddress((void**)&woh, g_woh);
    cudaGetSymbolAddress((void**)&wol, g_wol);
    float* gy;
    cudaGetSymbolAddress((void**)&gy, g_Y);

    rope_table_kernel<<<(SEQ * HDIM + 255) / 256, 256>>>();

    // preconvert: x and weights to split bf16
    split_kernel<<<(BT * DMODEL / 4 + 255) / 256, 256>>>(x, xh, xl, BT * DMODEL);
    tsplit_kernel<<<dim3(N_QKV / 32, DMODEL / 32), dim3(32, 8)>>>(
        w_qkv, wqh, wql, DMODEL, N_QKV);
    tsplit_kernel<<<dim3(DMODEL / 32, DMODEL / 32), dim3(32, 8)>>>(
        w_out, woh, wol, DMODEL, DMODEL);

    // QKV GEMM + RoPE/scatter
    mma_gemm_kernel<1><<<dim3(N_QKV / 128, BT / 128), 256, GEMM_SMEM>>>(
        xh, xl, wqh, wql, nullptr, BT, N_QKV, DMODEL);

    // attention
    attn_kernel<<<dim3(SEQ / 128, NHEAD, BATCH), 256, ATT_SMEM>>>();

    // split y, then output projection
    split_kernel<<<(BT * DMODEL / 4 + 255) / 256, 256>>>(gy, yh, yl, BT * DMODEL);
    mma_gemm_kernel<2><<<dim3(DMODEL / 128, BT / 128), 256, GEMM_SMEM>>>(
        yh, yl, woh, wol, out, BT, DMODEL, DMODEL);
}

// round 6
// speedup vs baseline: 2.5744x; 1.8579x over previous
#include <cuda_runtime.h>
#include <cuda_bf16.h>
#include <math.h>
#include <stdint.h>

#define BATCH   2
#define SEQ     2048
#define DMODEL  1024
#define NHEAD   16
#define HDIM    64
#define BT      (BATCH * SEQ)          // 4096
#define N_QKV   (3 * DMODEL)           // 3072

// split-bf16 tensors
__device__ __nv_bfloat16 g_Qh[BATCH * NHEAD * SEQ * HDIM];  // [b,h,t,d], pre-scaled 1/8
__device__ __nv_bfloat16 g_Ql[BATCH * NHEAD * SEQ * HDIM];
__device__ __nv_bfloat16 g_Kh[BATCH * NHEAD * SEQ * HDIM];  // [b,h,t,d]
__device__ __nv_bfloat16 g_Kl[BATCH * NHEAD * SEQ * HDIM];
__device__ __nv_bfloat16 g_Vth[BATCH * NHEAD * HDIM * SEQ]; // [b,h,d,t] (transposed)
__device__ __nv_bfloat16 g_Vtl[BATCH * NHEAD * HDIM * SEQ];
__device__ __nv_bfloat16 g_xh[BT * DMODEL];
__device__ __nv_bfloat16 g_xl[BT * DMODEL];
__device__ __nv_bfloat16 g_yh[BT * DMODEL];
__device__ __nv_bfloat16 g_yl[BT * DMODEL];
__device__ __nv_bfloat16 g_wqh[N_QKV * DMODEL];     // transposed [n][k]
__device__ __nv_bfloat16 g_wql[N_QKV * DMODEL];
__device__ __nv_bfloat16 g_woh[DMODEL * DMODEL];    // transposed [n][k]
__device__ __nv_bfloat16 g_wol[DMODEL * DMODEL];
__device__ float g_cos[SEQ * HDIM];
__device__ float g_sin[SEQ * HDIM];

// ---------------------------------------------------------------------------
__device__ __forceinline__ void split2(float v, __nv_bfloat16& h, __nv_bfloat16& l) {
    h = __float2bfloat16(v);
    l = __float2bfloat16(v - __bfloat162float(h));
}
__device__ __forceinline__ uint32_t pack2(__nv_bfloat16 a, __nv_bfloat16 b) {
    uint16_t ua = *reinterpret_cast<uint16_t*>(&a);
    uint16_t ub = *reinterpret_cast<uint16_t*>(&b);
    return (uint32_t)ua | ((uint32_t)ub << 16);
}

__global__ void rope_table_kernel() {
    int i = blockIdx.x * blockDim.x + threadIdx.x;
    if (i >= SEQ * HDIM) return;
    int t = i >> 6;
    int d = i & 63;
    int fi = (d < 32) ? d : d - 32;
    float inv = powf(10000.0f, -((float)fi) / 32.0f);
    float ang = (float)t * inv;
    g_cos[i] = cosf(ang);
    g_sin[i] = sinf(ang);
}

__global__ void split_kernel(const float* __restrict__ in,
                             __nv_bfloat16* __restrict__ hi,
                             __nv_bfloat16* __restrict__ lo, int n)
{
    int i = (blockIdx.x * blockDim.x + threadIdx.x) * 4;
    if (i >= n) return;
    float4 v = *reinterpret_cast<const float4*>(in + i);
    __nv_bfloat16 h[4], l[4];
    split2(v.x, h[0], l[0]); split2(v.y, h[1], l[1]);
    split2(v.z, h[2], l[2]); split2(v.w, h[3], l[3]);
    *reinterpret_cast<uint2*>(hi + i) = *reinterpret_cast<uint2*>(h);
    *reinterpret_cast<uint2*>(lo + i) = *reinterpret_cast<uint2*>(l);
}

__global__ void tsplit_kernel(const float* __restrict__ W,
                              __nv_bfloat16* __restrict__ th,
                              __nv_bfloat16* __restrict__ tl, int K, int N)
{
    __shared__ float tile[32][33];
    const int n0 = blockIdx.x * 32;
    const int k0 = blockIdx.y * 32;
    const int tx = threadIdx.x, ty = threadIdx.y;
    #pragma unroll
    for (int j = 0; j < 4; j++)
        tile[ty + j * 8][tx] = W[(size_t)(k0 + ty + j * 8) * N + n0 + tx];
    __syncthreads();
    #pragma unroll
    for (int j = 0; j < 4; j++) {
        float v = tile[tx][ty + j * 8];
        __nv_bfloat16 h, l;
        split2(v, h, l);
        size_t o = (size_t)(n0 + ty + j * 8) * K + k0 + tx;
        th[o] = h;
        tl[o] = l;
    }
}

// ===========================================================================
#define CP16(dst, src) \
    asm volatile("cp.async.cg.shared.global [%0], [%1], 16;" \
                 :: "r"(dst), "l"(src))
#define CP_COMMIT() asm volatile("cp.async.commit_group;")
#define CP_WAIT1()  asm volatile("cp.async.wait_group 1;")
#define CP_WAIT0()  asm volatile("cp.async.wait_group 0;")

__device__ __forceinline__ void mma16816(float* c, const uint32_t* a, const uint32_t* b) {
    asm volatile(
        "mma.sync.aligned.m16n8k16.row.col.f32.bf16.bf16.f32 "
        "{%0,%1,%2,%3}, {%4,%5,%6,%7}, {%8,%9}, {%0,%1,%2,%3};"
        : "+f"(c[0]), "+f"(c[1]), "+f"(c[2]), "+f"(c[3])
        : "r"(a[0]), "r"(a[1]), "r"(a[2]), "r"(a[3]), "r"(b[0]), "r"(b[1]));
}

// ===========================================================================
// mma.sync split-bf16 GEMM (as round 5), EPI=1 epilogue now writes split bf16
// Q (scaled), K, and transposed V.
// ===========================================================================
#define ROWB   80
#define ARRB   (128 * ROWB)
#define STAGEB (4 * ARRB)
#define GEMM_SMEM (2 * STAGEB)

template <int EPI>
__global__ __launch_bounds__(256, 1)
void mma_gemm_kernel(const __nv_bfloat16* __restrict__ Ah_g,
                     const __nv_bfloat16* __restrict__ Al_g,
                     const __nv_bfloat16* __restrict__ Bh_g,
                     const __nv_bfloat16* __restrict__ Bl_g,
                     float* __restrict__ C, int M, int N, int K)
{
    extern __shared__ char smc[];
    const uint32_t smem_u32 = (uint32_t)__cvta_generic_to_shared(smc);

    const int tid  = threadIdx.x;
    const int lane = tid & 31;
    const int wid  = tid >> 5;
    const int wm   = wid & 1;
    const int wn   = wid >> 1;
    const int g    = lane >> 2;
    const int t    = lane & 3;
    const int m0   = blockIdx.y * 128;
    const int n0   = blockIdx.x * 128;

    const int ld_row = tid >> 2;
    const int ld_seg = tid & 3;

    float acc[4][4][4];
    #pragma unroll
    for (int a = 0; a < 4; a++)
        #pragma unroll
        for (int b = 0; b < 4; b++)
            #pragma unroll
            for (int c = 0; c < 4; c++) acc[a][b][c] = 0.0f;

    #define LOAD_STAGE(kt, s) do {                                            \
        uint32_t sb = smem_u32 + (s) * STAGEB;                                \
        _Pragma("unroll")                                                     \
        for (int i = 0; i < 2; i++) {                                         \
            int row = ld_row + i * 64;                                        \
            uint32_t so = sb + row * ROWB + ld_seg * 16;                      \
            size_t  ga = (size_t)(m0 + row) * K + (kt) * 32 + ld_seg * 8;     \
            size_t  gb = (size_t)(n0 + row) * K + (kt) * 32 + ld_seg * 8;     \
            CP16(so,            Ah_g + ga);                                   \
            CP16(so + ARRB,     Al_g + ga);                                   \
            CP16(so + 2 * ARRB, Bh_g + gb);                                   \
            CP16(so + 3 * ARRB, Bl_g + gb);                                   \
        }                                                                     \
    } while (0)

    const int nk = K >> 5;
    LOAD_STAGE(0, 0);
    CP_COMMIT();

    for (int kt = 0; kt < nk; kt++) {
        const int s = kt & 1;
        if (kt + 1 < nk) {
            LOAD_STAGE(kt + 1, s ^ 1);
            CP_COMMIT();
            CP_WAIT1();
        } else {
            CP_WAIT0();
        }
        __syncthreads();

        const char* st  = smc + s * STAGEB;
        const char* pAh = st;
        const char* pAl = st + ARRB;
        const char* pBh = st + 2 * ARRB;
        const char* pBl = st + 3 * ARRB;

        #pragma unroll
        for (int ks = 0; ks < 2; ks++) {
            const int kb = ks * 32;
            uint32_t af_h[4][4], af_l[4][4], bf_h[4][2], bf_l[4][2];
            #pragma unroll
            for (int mt = 0; mt < 4; mt++) {
                int off = (wm * 64 + mt * 16 + g) * ROWB + kb + t * 4;
                af_h[mt][0] = *(const uint32_t*)(pAh + off);
                af_h[mt][1] = *(const uint32_t*)(pAh + off + 8 * ROWB);
                af_h[mt][2] = *(const uint32_t*)(pAh + off + 16);
                af_h[mt][3] = *(const uint32_t*)(pAh + off + 8 * ROWB + 16);
                af_l[mt][0] = *(const uint32_t*)(pAl + off);
                af_l[mt][1] = *(const uint32_t*)(pAl + off + 8 * ROWB);
                af_l[mt][2] = *(const uint32_t*)(pAl + off + 16);
                af_l[mt][3] = *(const uint32_t*)(pAl + off + 8 * ROWB + 16);
            }
            #pragma unroll
            for (int nt = 0; nt < 4; nt++) {
                int off = (wn * 32 + nt * 8 + g) * ROWB + kb + t * 4;
                bf_h[nt][0] = *(const uint32_t*)(pBh + off);
                bf_h[nt][1] = *(const uint32_t*)(pBh + off + 16);
                bf_l[nt][0] = *(const uint32_t*)(pBl + off);
                bf_l[nt][1] = *(const uint32_t*)(pBl + off + 16);
            }
            #pragma unroll
            for (int mt = 0; mt < 4; mt++)
                #pragma unroll
                for (int nt = 0; nt < 4; nt++) {
                    mma16816(acc[mt][nt], af_h[mt], bf_h[nt]);
                    mma16816(acc[mt][nt], af_h[mt], bf_l[nt]);
                    mma16816(acc[mt][nt], af_l[mt], bf_h[nt]);
                }
        }
        __syncthreads();
    }
    #undef LOAD_STAGE

    #pragma unroll
    for (int mt = 0; mt < 4; mt++) {
        const int mr0 = m0 + wm * 64 + mt * 16 + g;
        #pragma unroll
        for (int nt = 0; nt < 4; nt++) {
            const int col = n0 + wn * 32 + nt * 8 + 2 * t;
            const float* a = acc[mt][nt];
            if (EPI == 2) {
                *reinterpret_cast<float2*>(C + (size_t)mr0 * N + col) =
                    make_float2(a[0], a[1]);
                *reinterpret_cast<float2*>(C + (size_t)(mr0 + 8) * N + col) =
                    make_float2(a[2], a[3]);
            } else {
                const int section = col >> 10;
                const int within  = col & 1023;
                const int h       = within >> 6;
                const int d       = within & 63;      // even
                #pragma unroll
                for (int rr = 0; rr < 2; rr++) {
                    const int m  = mr0 + rr * 8;
                    const int bb = m >> 11;
                    const int tt = m & 2047;
                    float e = a[rr * 2 + 0], o = a[rr * 2 + 1];
                    if (section == 2) {
                        // transposed split V: [b,h,d,t]
                        size_t vb = ((size_t)(bb * NHEAD + h) * HDIM + d) * SEQ + tt;
                        __nv_bfloat16 h0, l0, h1, l1;
                        split2(e, h0, l0);
                        split2(o, h1, l1);
                        g_Vth[vb]       = h0;
                        g_Vtl[vb]       = l0;
                        g_Vth[vb + SEQ] = h1;
                        g_Vtl[vb + SEQ] = l1;
                    } else {
                        int idx = tt * HDIM + d;
                        float c0 = g_cos[idx],     s0 = g_sin[idx];
                        float c1 = g_cos[idx + 1], s1 = g_sin[idx + 1];
                        float r0 = e * c0 - o * s0;
                        float r1 = o * c1 + e * s1;
                        size_t base = ((size_t)(bb * NHEAD + h) * SEQ + tt) * HDIM + d;
                        __nv_bfloat16 h0, l0, h1, l1;
                        if (section == 0) {       // Q: fold softmax scale
                            r0 *= 0.125f; r1 *= 0.125f;
                            split2(r0, h0, l0); split2(r1, h1, l1);
                            *reinterpret_cast<uint32_t*>(g_Qh + base) = pack2(h0, h1);
                            *reinterpret_cast<uint32_t*>(g_Ql + base) = pack2(l0, l1);
                        } else {
                            split2(r0, h0, l0); split2(r1, h1, l1);
                            *reinterpret_cast<uint32_t*>(g_Kh + base) = pack2(h0, h1);
                            *reinterpret_cast<uint32_t*>(g_Kl + base) = pack2(l0, l1);
                        }
                    }
                }
            }
        }
    }
}

// ===========================================================================
// Tensor-core flash attention.
// CTA: 128 q-rows x (head, batch); 8 warps, each owns 16 full q-rows.
// S = QhKh + QhKl + QlKh; P split in regs; O += PhVh + PhVl + PlVh.
// K smem rows padded to 144B, Vt rows to 272B (conflict-free frag LDS).
// ===========================================================================
#define KROW    144
#define VROW    272
#define KTILE_B (128 * KROW)            // 18432
#define VTILE_B (64 * VROW)             // 17408
#define ATT_STAGE (2 * KTILE_B + 2 * VTILE_B)   // 71680
#define ATT_SMEM  (2 * ATT_STAGE)               // 143360

__global__ __launch_bounds__(256, 1)
void attn_mma_kernel()
{
    extern __shared__ char smc[];
    const uint32_t smem_u32 = (uint32_t)__cvta_generic_to_shared(smc);

    const int tid  = threadIdx.x;
    const int lane = tid & 31;
    const int w    = tid >> 5;           // warp 0..7 -> q rows w*16..w*16+15
    const int g    = lane >> 2;
    const int t    = lane & 3;
    const int qt   = blockIdx.x;         // 0..15
    const int hh   = blockIdx.y;
    const int bb   = blockIdx.z;

    const size_t head_base = (size_t)(bb * NHEAD + hh) * SEQ * HDIM;   // Q/K elems
    const size_t vt_base   = (size_t)(bb * NHEAD + hh) * HDIM * SEQ;   // Vt elems

    // ---- Q fragments (held in registers for the whole kernel) ----
    uint32_t qh[4][4], ql[4][4];
    {
        const int r0 = qt * 128 + w * 16 + g;
        const char* pqh = (const char*)(g_Qh + head_base);
        const char* pql = (const char*)(g_Ql + head_base);
        #pragma unroll
        for (int ks = 0; ks < 4; ks++) {
            int o00 = r0 * 128 + ks * 32 + t * 4;          // bytes (row stride 64*2)
            int o10 = o00 + 8 * 128;
            qh[ks][0] = *(const uint32_t*)(pqh + o00);
            qh[ks][1] = *(const uint32_t*)(pqh + o10);
            qh[ks][2] = *(const uint32_t*)(pqh + o00 + 16);
            qh[ks][3] = *(const uint32_t*)(pqh + o10 + 16);
            ql[ks][0] = *(const uint32_t*)(pql + o00);
            ql[ks][1] = *(const uint32_t*)(pql + o10);
            ql[ks][2] = *(const uint32_t*)(pql + o00 + 16);
            ql[ks][3] = *(const uint32_t*)(pql + o10 + 16);
        }
    }

    // online softmax state: thread owns rows g (idx 0) and g+8 (idx 1)
    float m_[2] = {-INFINITY, -INFINITY};
    float l_[2] = {0.0f, 0.0f};
    float o[8][4];
    #pragma unroll
    for (int nt = 0; nt < 8; nt++)
        #pragma unroll
        for (int c = 0; c < 4; c++) o[nt][c] = 0.0f;

    // KV loader: per stage, 4 arrays (Kh,Kl 128x8 chunks; Vth,Vtl 64x16 chunks)
    #define LOAD_KV(kt, s) do {                                               \
        uint32_t sb = smem_u32 + (s) * ATT_STAGE;                             \
        _Pragma("unroll")                                                     \
        for (int i = 0; i < 4; i++) {                                         \
            int c    = tid + i * 256;              /* 0..1023 */              \
            int krow = c >> 3, kcc = c & 7;                                   \
            size_t kg = head_base + (size_t)((kt) * 128 + krow) * 64 + kcc * 8; \
            uint32_t kd = sb + krow * KROW + kcc * 16;                        \
            CP16(kd,            g_Kh + kg);                                   \
            CP16(kd + KTILE_B,  g_Kl + kg);                                   \
            int vrow = c >> 4, vcc = c & 15;                                  \
            size_t vg = vt_base + (size_t)vrow * SEQ + (kt) * 128 + vcc * 8;  \
            uint32_t vd = sb + 2 * KTILE_B + vrow * VROW + vcc * 16;          \
            CP16(vd,            g_Vth + vg);                                  \
            CP16(vd + VTILE_B,  g_Vtl + vg);                                  \
        }                                                                     \
    } while (0)

    LOAD_KV(0, 0);
    CP_COMMIT();

    for (int kt = 0; kt < SEQ / 128; kt++) {
        const int s = kt & 1;
        if (kt + 1 < SEQ / 128) {
            LOAD_KV(kt + 1, s ^ 1);
            CP_COMMIT();
            CP_WAIT1();
        } else {
            CP_WAIT0();
        }
        __syncthreads();

        const char* st   = smc + s * ATT_STAGE;
        const char* pKh  = st;
        const char* pKl  = st + KTILE_B;
        const char* pVh  = st + 2 * KTILE_B;
        const char* pVl  = st + 2 * KTILE_B + VTILE_B;

        // ---- S = Q K^T : 16 n-tiles x 4 k-steps x 3 ----
        float sacc[16][4];
        #pragma unroll
        for (int nt = 0; nt < 16; nt++)
            #pragma unroll
            for (int c = 0; c < 4; c++) sacc[nt][c] = 0.0f;

        #pragma unroll
        for (int nt = 0; nt < 16; nt++) {
            const int rowb = (nt * 8 + g) * KROW + t * 4;
            #pragma unroll
            for (int ks = 0; ks < 4; ks++) {
                uint32_t bh[2], bl[2];
                bh[0] = *(const uint32_t*)(pKh + rowb + ks * 32);
                bh[1] = *(const uint32_t*)(pKh + rowb + ks * 32 + 16);
                bl[0] = *(const uint32_t*)(pKl + rowb + ks * 32);
                bl[1] = *(const uint32_t*)(pKl + rowb + ks * 32 + 16);
                mma16816(sacc[nt], qh[ks], bh);
                mma16816(sacc[nt], qh[ks], bl);
                mma16816(sacc[nt], ql[ks], bh);
            }
        }

        // ---- online softmax (warp owns full rows; reduce over 4 t-lanes) ----
        float alpha[2];
        #pragma unroll
        for (int rr = 0; rr < 2; rr++) {
            float mx = -INFINITY;
            #pragma unroll
            for (int nt = 0; nt < 16; nt++) {
                mx = fmaxf(mx, fmaxf(sacc[nt][rr * 2], sacc[nt][rr * 2 + 1]));
            }
            mx = fmaxf(mx, __shfl_xor_sync(0xffffffffu, mx, 1));
            mx = fmaxf(mx, __shfl_xor_sync(0xffffffffu, mx, 2));
            float mnew = fmaxf(m_[rr], mx);
            alpha[rr] = __expf(m_[rr] - mnew);
            float sum = 0.0f;
            #pragma unroll
            for (int nt = 0; nt < 16; nt++) {
                float p0 = __expf(sacc[nt][rr * 2]     - mnew);
                float p1 = __expf(sacc[nt][rr * 2 + 1] - mnew);
                sacc[nt][rr * 2]     = p0;
                sacc[nt][rr * 2 + 1] = p1;
                sum += p0 + p1;
            }
            sum += __shfl_xor_sync(0xffffffffu, sum, 1);
            sum += __shfl_xor_sync(0xffffffffu, sum, 2);
            l_[rr] = l_[rr] * alpha[rr] + sum;
            m_[rr] = mnew;
        }
        #pragma unroll
        for (int nt = 0; nt < 8; nt++) {
            o[nt][0] *= alpha[0]; o[nt][1] *= alpha[0];
            o[nt][2] *= alpha[1]; o[nt][3] *= alpha[1];
        }

        // ---- P -> split bf16 A-fragments (register-only) ----
        uint32_t aph[8][4], apl[8][4];
        #pragma unroll
        for (int j = 0; j < 8; j++) {
            #pragma unroll
            for (int half = 0; half < 2; half++) {      // s-tiles 2j, 2j+1
                const float* sv = sacc[2 * j + half];
                __nv_bfloat16 h0, l0, h1, l1;
                split2(sv[0], h0, l0); split2(sv[1], h1, l1);
                aph[j][half * 2 + 0] = pack2(h0, h1);   // wait: order below
                apl[j][half * 2 + 0] = pack2(l0, l1);
                split2(sv[2], h0, l0); split2(sv[3], h1, l1);
                aph[j][half * 2 + 1] = pack2(h0, h1);
                apl[j][half * 2 + 1] = pack2(l0, l1);
            }
        }
        // fragment order fix: a = {tile2j rows g / g+8, tile2j+1 rows g / g+8}
        // mapping above already yields [0]=t2j row g, [1]=t2j row g+8,
        //                              [2]=t2j+1 row g, [3]=t2j+1 row g+8  ✓

        // ---- O += P V : 8 k-tiles x 8 n-tiles x 3 ----
        #pragma unroll
        for (int j = 0; j < 8; j++) {
            #pragma unroll
            for (int nt = 0; nt < 8; nt++) {
                const int rowb = (nt * 8 + g) * VROW + j * 32 + t * 4;
                uint32_t bh[2], bl[2];
                bh[0] = *(const uint32_t*)(pVh + rowb);
                bh[1] = *(const uint32_t*)(pVh + rowb + 16);
                bl[0] = *(const uint32_t*)(pVl + rowb);
                bl[1] = *(const uint32_t*)(pVl + rowb + 16);
                mma16816(o[nt], aph[j], bh);
                mma16816(o[nt], aph[j], bl);
                mma16816(o[nt], apl[j], bh);
            }
        }
        __syncthreads();
    }

    // ---- epilogue: split y directly to g_yh/g_yl ----
    const float inv0 = 1.0f / l_[0];
    const float inv1 = 1.0f / l_[1];
    #pragma unroll
    for (int rr = 0; rr < 2; rr++) {
        const int row = qt * 128 + w * 16 + g + rr * 8;
        const float inv = rr ? inv1 : inv0;
        size_t base = ((size_t)bb * SEQ + row) * DMODEL + hh * HDIM;
        #pragma unroll
        for (int nt = 0; nt < 8; nt++) {
            const int d = nt * 8 + 2 * t;
            float y0 = o[nt][rr * 2]     * inv;
            float y1 = o[nt][rr * 2 + 1] * inv;
            __nv_bfloat16 h0, l0, h1, l1;
            split2(y0, h0, l0); split2(y1, h1, l1);
            *reinterpret_cast<uint32_t*>(g_yh + base + d) = pack2(h0, h1);
            *reinterpret_cast<uint32_t*>(g_yl + base + d) = pack2(l0, l1);
        }
    }
}

// ---------------------------------------------------------------------------
extern "C" void kernel_launch(void* const* d_in, const int* in_sizes, int n_in,
                              void* d_out, int out_size)
{
    const float* x     = (const float*)d_in[0];
    const float* w_qkv = (const float*)d_in[1];
    const float* w_out = (const float*)d_in[2];
    float* out = (float*)d_out;

    static bool attr_done = false;
    if (!attr_done) {
        cudaFuncSetAttribute(mma_gemm_kernel<1>,
                             cudaFuncAttributeMaxDynamicSharedMemorySize, GEMM_SMEM);
        cudaFuncSetAttribute(mma_gemm_kernel<2>,
                             cudaFuncAttributeMaxDynamicSharedMemorySize, GEMM_SMEM);
        cudaFuncSetAttribute(attn_mma_kernel,
                             cudaFuncAttributeMaxDynamicSharedMemorySize, ATT_SMEM);
        attr_done = true;
    }

    __nv_bfloat16 *xh, *xl, *yh, *yl, *wqh, *wql, *woh, *wol;
    cudaGetSymbolAddress((void**)&xh,  g_xh);
    cudaGetSymbolAddress((void**)&xl,  g_xl);
    cudaGetSymbolAddress((void**)&yh,  g_yh);
    cudaGetSymbolAddress((void**)&yl,  g_yl);
    cudaGetSymbolAddress((void**)&wqh, g_wqh);
    cudaGetSymbolAddress((void**)&wql, g_wql);
    cudaGetSymbolAddress((void**)&woh, g_woh);
    cudaGetSymbolAddress((void**)&wol, g_wol);

    rope_table_kernel<<<(SEQ * HDIM + 255) / 256, 256>>>();

    split_kernel<<<(BT * DMODEL / 4 + 255) / 256, 256>>>(x, xh, xl, BT * DMODEL);
    tsplit_kernel<<<dim3(N_QKV / 32, DMODEL / 32), dim3(32, 8)>>>(
        w_qkv, wqh, wql, DMODEL, N_QKV);
    tsplit_kernel<<<dim3(DMODEL / 32, DMODEL / 32), dim3(32, 8)>>>(
        w_out, woh, wol, DMODEL, DMODEL);

    mma_gemm_kernel<1><<<dim3(N_QKV / 128, BT / 128), 256, GEMM_SMEM>>>(
        xh, xl, wqh, wql, nullptr, BT, N_QKV, DMODEL);

    attn_mma_kernel<<<dim3(SEQ / 128, NHEAD, BATCH), 256, ATT_SMEM>>>();

    mma_gemm_kernel<2><<<dim3(DMODEL / 128, BT / 128), 256, GEMM_SMEM>>>(
        yh, yl, woh, wol, out, BT, DMODEL, DMODEL);
}